// round 16
// baseline (speedup 1.0000x reference)
#include <cuda_runtime.h>
#include <math.h>

#define NB 8
#define NT 256
#define NDI 64
#define ND 128
#define NROWS (NB*NT)
#define NOUT 672

__device__ float g_fm[NROWS*ND];
__device__ float g_k[NROWS*ND];
__device__ float g_v[NROWS*ND];
__device__ float g_theta[NROWS];
__device__ float g_eta[NROWS];
__device__ float g_alpha[NROWS];
__device__ float g_qlast[NB*ND];
__device__ float g_flast[NB*ND];
__device__ float g_hh[NB*ND];
__device__ float g_G[NB*NT*NT];
__device__ float g_X[NB*8*32*32];
__device__ float g_Gq[NB*NT];
__device__ int   g_ctr[16];      // [0..7] tail gates, [8] head gate
__device__ int   g_ctrf[32];

__device__ __forceinline__ float gelu_t(float x) {
    float x3 = x*x*x;
    return 0.5f*x*(1.0f + tanhf(0.79788456080286535588f*(x + 0.044715f*x3)));
}
__device__ __forceinline__ float sigmoid_f(float x) {
    return 1.0f/(1.0f + expf(-x));
}

// =====================================================================
// Launch 1: mega3 — 128 CTAs = 32 row-blocks x 4 subs (co-resident).
// Resets g_ctr (incl. head gate [8]) for this call.
// =====================================================================
__global__ __launch_bounds__(256, 1) void mega3_kernel(
    const float* __restrict__ x,  const float* __restrict__ W_b,
    const float* __restrict__ b_b,
    const float* __restrict__ Wk, const float* __restrict__ Wv,
    const float* __restrict__ Wq,
    const float* __restrict__ Wm, const float* __restrict__ bm_)
{
    __shared__ __align__(16) float pool[9216];

    int tid = threadIdx.x;
    int idx = blockIdx.x;
    if (idx == 0 && tid < 16) g_ctr[tid] = 0;

    int rb = idx >> 2, sub = idx & 3;
    int row0 = rb * 64;
    int srow0 = row0 + sub * 16;

    // ---------------- Phase A: f slice (16 x 128) ----------------
    {
        float* Wbs = pool;
        float* xs  = pool + 8192;
        const float4* Wb4 = (const float4*)W_b;
#pragma unroll
        for (int rep = 0; rep < 8; ++rep)
            ((float4*)Wbs)[rep * 256 + tid] = Wb4[rep * 256 + tid];
        {
            int r = tid >> 4, q = (tid & 15) * 4;
            *(float4*)(xs + r * 64 + q) =
                *(const float4*)(x + (size_t)(srow0 + r) * NDI + q);
        }
        __syncthreads();

        int r = tid >> 4;
        int cg = (tid & 15) * 8;
        float acc[8];
#pragma unroll
        for (int j = 0; j < 8; ++j) acc[j] = 0.f;
#pragma unroll 8
        for (int k = 0; k < NDI; ++k) {
            float a = xs[r * 64 + k];
            float4 w0 = *(const float4*)(Wbs + k * 128 + cg);
            float4 w1 = *(const float4*)(Wbs + k * 128 + cg + 4);
            acc[0] = fmaf(a, w0.x, acc[0]);
            acc[1] = fmaf(a, w0.y, acc[1]);
            acc[2] = fmaf(a, w0.z, acc[2]);
            acc[3] = fmaf(a, w0.w, acc[3]);
            acc[4] = fmaf(a, w1.x, acc[4]);
            acc[5] = fmaf(a, w1.y, acc[5]);
            acc[6] = fmaf(a, w1.z, acc[6]);
            acc[7] = fmaf(a, w1.w, acc[7]);
        }
        float4 bb0 = *(const float4*)(b_b + cg);
        float4 bb1 = *(const float4*)(b_b + cg + 4);
        float4 o0, o1;
        o0.x = gelu_t(acc[0] + bb0.x);
        o0.y = gelu_t(acc[1] + bb0.y);
        o0.z = gelu_t(acc[2] + bb0.z);
        o0.w = gelu_t(acc[3] + bb0.w);
        o1.x = gelu_t(acc[4] + bb1.x);
        o1.y = gelu_t(acc[5] + bb1.y);
        o1.z = gelu_t(acc[6] + bb1.z);
        o1.w = gelu_t(acc[7] + bb1.w);
        *(float4*)(g_fm + (size_t)(srow0 + r) * ND + cg)     = o0;
        *(float4*)(g_fm + (size_t)(srow0 + r) * ND + cg + 4) = o1;
    }

    __threadfence();
    __syncthreads();
    if (tid == 0) {
        atomicAdd(&g_ctrf[rb], 1);
        while (atomicAdd(&g_ctrf[rb], 0) < 4) __nanosleep(64);
    }
    __syncthreads();
    __threadfence();

    // ---------------- Phase B: kv quarter (64x64, K=128) -------------
    {
        const float* Bmw = (sub >> 1) ? Wv : Wk;
        float* Cout = (sub >> 1) ? g_v : g_k;
        int bn = (sub & 1) * 64;
        float* As_ = pool;
        float* Bs_ = pool + 1024;
        int ar = tid >> 2, ac = (tid & 3) * 4;
        int br = tid >> 4, bc4 = (tid & 15) * 4;
        int rm = (tid >> 4) * 4, rn = (tid & 15) * 4;

        float acc[4][4];
#pragma unroll
        for (int i = 0; i < 4; ++i)
#pragma unroll
            for (int j = 0; j < 4; ++j) acc[i][j] = 0.f;

        float4 pa = *(const float4*)(g_fm + (size_t)(row0 + ar) * ND + ac);
        float4 pb = *(const float4*)(Bmw + (size_t)br * ND + bn + bc4);
        for (int k0 = 0; k0 < ND; k0 += 16) {
            __syncthreads();
            As_[(ac+0)*64 + ar] = pa.x;
            As_[(ac+1)*64 + ar] = pa.y;
            As_[(ac+2)*64 + ar] = pa.z;
            As_[(ac+3)*64 + ar] = pa.w;
            *(float4*)(Bs_ + br*64 + bc4) = pb;
            __syncthreads();
            if (k0 + 16 < ND) {
                pa = *(const float4*)(g_fm + (size_t)(row0 + ar) * ND + k0 + 16 + ac);
                pb = *(const float4*)(Bmw + (size_t)(k0 + 16 + br) * ND + bn + bc4);
            }
#pragma unroll
            for (int kk = 0; kk < 16; ++kk) {
                float4 av = *(const float4*)(As_ + kk*64 + rm);
                float4 bv = *(const float4*)(Bs_ + kk*64 + rn);
                acc[0][0]=fmaf(av.x,bv.x,acc[0][0]); acc[0][1]=fmaf(av.x,bv.y,acc[0][1]);
                acc[0][2]=fmaf(av.x,bv.z,acc[0][2]); acc[0][3]=fmaf(av.x,bv.w,acc[0][3]);
                acc[1][0]=fmaf(av.y,bv.x,acc[1][0]); acc[1][1]=fmaf(av.y,bv.y,acc[1][1]);
                acc[1][2]=fmaf(av.y,bv.z,acc[1][2]); acc[1][3]=fmaf(av.y,bv.w,acc[1][3]);
                acc[2][0]=fmaf(av.z,bv.x,acc[2][0]); acc[2][1]=fmaf(av.z,bv.y,acc[2][1]);
                acc[2][2]=fmaf(av.z,bv.z,acc[2][2]); acc[2][3]=fmaf(av.z,bv.w,acc[2][3]);
                acc[3][0]=fmaf(av.w,bv.x,acc[3][0]); acc[3][1]=fmaf(av.w,bv.y,acc[3][1]);
                acc[3][2]=fmaf(av.w,bv.z,acc[3][2]); acc[3][3]=fmaf(av.w,bv.w,acc[3][3]);
            }
        }
#pragma unroll
        for (int i = 0; i < 4; ++i) {
            float4 o;
            o.x = acc[i][0]; o.y = acc[i][1]; o.z = acc[i][2]; o.w = acc[i][3];
            *(float4*)(Cout + (size_t)(row0 + rm + i) * ND + bn + rn) = o;
        }
    }

    // ---------------- meta (sub 0) ----------------
    if (sub == 0) {
        int warp = tid >> 5, lane = tid & 31;
        const float* wp = Wm + lane * 12;
        float w0=wp[0],w1=wp[1],w2=wp[2],w3=wp[3],w4=wp[4],w5=wp[5];
        float w6=wp[6],w7=wp[7],w8=wp[8],w9=wp[9],w10=wp[10],w11=wp[11];
#pragma unroll
        for (int rr = 0; rr < 8; ++rr) {
            int row = row0 + warp * 8 + rr;
            float4 fv = ((const float4*)(g_fm + (size_t)row * ND))[lane];
            float d0 = fv.x*w0 + fv.y*w3 + fv.z*w6 + fv.w*w9;
            float d1 = fv.x*w1 + fv.y*w4 + fv.z*w7 + fv.w*w10;
            float d2 = fv.x*w2 + fv.y*w5 + fv.z*w8 + fv.w*w11;
#pragma unroll
            for (int o = 16; o > 0; o >>= 1) {
                d0 += __shfl_xor_sync(0xffffffffu, d0, o);
                d1 += __shfl_xor_sync(0xffffffffu, d1, o);
                d2 += __shfl_xor_sync(0xffffffffu, d2, o);
            }
            if (lane == 0) {
                g_theta[row] = 0.01f * sigmoid_f(d0 + bm_[0]);
                g_eta[row]   =         sigmoid_f(d1 + bm_[1]);
                g_alpha[row] = 0.1f  * sigmoid_f(d2 + bm_[2]);
            }
        }
    }

    // ---------------- qlast + f_last (sub 1, last row-block) ---------
    if (sub == 1 && (rb & 3) == 3) {
        int batch = rb >> 2;
        __syncthreads();
        float* fl = pool;
        float* part = pool + 128;
        if (tid < ND)
            fl[tid] = g_fm[(size_t)(row0 + 63) * ND + tid];
        __syncthreads();
        int j = tid & 127, hf = tid >> 7;
        float a = 0.f;
        int i0 = hf * 64;
#pragma unroll 8
        for (int i = 0; i < 64; ++i)
            a = fmaf(fl[i0 + i], Wq[(size_t)(i0 + i) * ND + j], a);
        part[hf * 128 + j] = a;
        __syncthreads();
        if (tid < ND) {
            g_qlast[batch * ND + tid] = part[tid] + part[128 + tid];
            g_flast[batch * ND + tid] = fl[tid];
        }
    }
}

// =====================================================================
// zchunk: one fully-unrolled back-substitution chunk.
// =====================================================================
template<int C>
__device__ __forceinline__ void zchunk_f(
    const float* __restrict__ Gb, const float* __restrict__ Xob,
    float* Xc, float* pbuff, float* rbuf, float* zvec, const float* mc,
    const float* sA, const float* sB,
    const float (*sHc)[NT], const float (*sPPc)[NT],
    int tid, int u, int w)
{
    const float* Xo = Xob + (size_t)C * 1024;
#pragma unroll
    for (int rep = 0; rep < 4; ++rep) {
        int id2 = rep * 256 + tid;
        Xc[(id2 >> 5) * 33 + (id2 & 31)] = Xo[id2];
    }
    float acc = 0.f;
    constexpr int nj = 4 * (7 - C);
    int tauc = 32 * C + u;
#pragma unroll
    for (int j = 0; j < nj; ++j) {
        int t = 32 * (C + 1) + j * 8 + w;
        int Cr = t >> 5;
        float ht = fmaf(sA[t], sHc[Cr][tauc], sB[t] * sPPc[Cr][tauc]);
        float wv = Gb[(size_t)t * NT + tauc] * ht;
        acc = fmaf(wv, zvec[t], acc);
    }
    pbuff[w * 33 + u] = acc;
    __syncthreads();
    if (tid < 32) {
        float s = mc[32*C + tid];
#pragma unroll
        for (int p = 0; p < 8; ++p) s += pbuff[p * 33 + tid];
        rbuf[tid] = s;
    }
    __syncthreads();
    {
        float a = 0.f;
#pragma unroll
        for (int q2 = 0; q2 < 4; ++q2) {
            int kk = w * 4 + q2;
            a = fmaf(Xc[kk * 33 + u], rbuf[kk], a);
        }
        pbuff[w * 33 + u] = a;
    }
    __syncthreads();
    if (tid < 32) {
        float s = 0.f;
#pragma unroll
        for (int p = 0; p < 8; ++p) s += pbuff[p * 33 + tid];
        zvec[32*C + tid] = s;
    }
    __syncthreads();
}

// cross 32x32 Gram block: rows chunk rc, cols chunk cc
__device__ __forceinline__ void cross_block(
    const float* __restrict__ Kb, float* __restrict__ Gb,
    float* pool, int rc, int cc, int tid)
{
    float* Ks = pool;
    float* Kt = pool + 4224;
    {
        int kr = tid >> 3, seg = (tid & 7) * 16;
        const float* srcR = Kb + (size_t)(32*rc + kr) * ND + seg;
        const float* srcC = Kb + (size_t)(32*cc + kr) * ND + seg;
#pragma unroll
        for (int p = 0; p < 4; ++p) {
            *(float4*)(Ks + kr*132 + seg + 4*p) = *(const float4*)(srcR + 4*p);
            *(float4*)(Kt + kr*132 + seg + 4*p) = *(const float4*)(srcC + 4*p);
        }
    }
    __syncthreads();
    {
        int i2 = tid >> 3, j2b = (tid & 7) * 4;
        float gq0=0.f, gq1=0.f, gq2=0.f, gq3=0.f;
#pragma unroll 8
        for (int d = 0; d < ND; ++d) {
            float a = Ks[i2*132 + d];
            gq0 = fmaf(a, Kt[(j2b+0)*132 + d], gq0);
            gq1 = fmaf(a, Kt[(j2b+1)*132 + d], gq1);
            gq2 = fmaf(a, Kt[(j2b+2)*132 + d], gq2);
            gq3 = fmaf(a, Kt[(j2b+3)*132 + d], gq3);
        }
        float4 o; o.x=gq0; o.y=gq1; o.z=gq2; o.w=gq3;
        *(float4*)(Gb + (size_t)(32*rc + i2) * NT + 32*cc + j2b) = o;
    }
    __syncthreads();
}

// =====================================================================
// Launch 2: gprep5 — 141 CTAs (all co-resident).
//   bx<120 : 8 batches x 15 tasks (6 tiles, 8 inv, 1 cross+Gq)
//            last arriver: coefs + z-solve + m_last + head chain -> g_hh
//   bx>=120: W2 column CTA: stage W2 slice, spin g_ctr[8]==8, out GEMM.
// =====================================================================
__global__ __launch_bounds__(256, 1) void gprep5_kernel(
    const float* __restrict__ W_f, const float* __restrict__ b_f,
    const float* __restrict__ W1,  const float* __restrict__ b1,
    const float* __restrict__ g1,  const float* __restrict__ be1,
    const float* __restrict__ W2,  const float* __restrict__ b2,
    float* __restrict__ out)
{
    __shared__ __align__(16) float pool[8832];
    __shared__ int sflag;

    int bx = blockIdx.x;
    int tid = threadIdx.x;

    if (bx >= 120) {
        // =========== W2 column CTA (co-resident spinner) ===========
        if (bx == 120 && tid < 32) g_ctrf[tid] = 0;   // reset for next mega

        int col0 = (bx - 120) * 32;
        float* w2s = pool;            // [128][33]
        float* hs  = pool + 4224;     // [8][132]

        // stage W2 slice immediately (independent of everything)
#pragma unroll
        for (int rep = 0; rep < 4; ++rep) {
            int id2 = rep * 256 + tid;
            int row = id2 >> 3;
            int quad = (id2 & 7) * 4;
            float4 v = *(const float4*)(W2 + (size_t)row * NOUT + col0 + quad);
            w2s[row*33 + quad + 0] = v.x;
            w2s[row*33 + quad + 1] = v.y;
            w2s[row*33 + quad + 2] = v.z;
            w2s[row*33 + quad + 3] = v.w;
        }

        if (tid == 0) {
            while (atomicAdd(&g_ctr[8], 0) < 8) __nanosleep(128);
        }
        __syncthreads();
        __threadfence();

#pragma unroll
        for (int rep = 0; rep < 4; ++rep) {
            int id2 = rep * 256 + tid;
            if (id2 < 1024) {
                int bb = id2 >> 7, i = id2 & 127;
                hs[bb * 132 + i] = g_hh[bb * ND + i];
            }
        }
        __syncthreads();

        int c = tid & 31, b = tid >> 5;
        float acc = b2[col0 + c];
#pragma unroll 16
        for (int i = 0; i < 128; ++i)
            acc = fmaf(hs[b * 132 + i], w2s[i * 33 + c], acc);
        out[b * NOUT + col0 + c] = acc;
        return;
    }

    int b = bx / 15;
    int r = bx % 15;
    const float* Kb = g_k + (size_t)b * NT * ND;
    float* Gb = g_G + (size_t)b * NT * NT;

    if (r < 6) {
        const int tiv[6] = {1, 2, 2, 3, 3, 3};
        const int tjv[6] = {0, 0, 1, 0, 1, 2};
        int I = tiv[r] * 64, J = tjv[r] * 64;
        float (*As)[64] = (float(*)[64])pool;
        float (*Bs)[64] = (float(*)[64])(pool + 1024);
        int ar = tid >> 2, ac = (tid & 3) * 4;
        int rm = (tid >> 4) * 4, rn = (tid & 15) * 4;

        float acc[4][4];
#pragma unroll
        for (int i = 0; i < 4; ++i)
#pragma unroll
            for (int j = 0; j < 4; ++j) acc[i][j] = 0.f;

        float4 pa = *(const float4*)(Kb + (size_t)(I + ar) * ND + ac);
        float4 pb = *(const float4*)(Kb + (size_t)(J + ar) * ND + ac);
        for (int k0 = 0; k0 < ND; k0 += 16) {
            __syncthreads();
            As[ac+0][ar]=pa.x; As[ac+1][ar]=pa.y; As[ac+2][ar]=pa.z; As[ac+3][ar]=pa.w;
            Bs[ac+0][ar]=pb.x; Bs[ac+1][ar]=pb.y; Bs[ac+2][ar]=pb.z; Bs[ac+3][ar]=pb.w;
            __syncthreads();
            if (k0 + 16 < ND) {
                pa = *(const float4*)(Kb + (size_t)(I + ar) * ND + k0 + 16 + ac);
                pb = *(const float4*)(Kb + (size_t)(J + ar) * ND + k0 + 16 + ac);
            }
#pragma unroll
            for (int kk = 0; kk < 16; ++kk) {
                float4 av = *(const float4*)(&As[kk][rm]);
                float4 bv = *(const float4*)(&Bs[kk][rn]);
                acc[0][0]=fmaf(av.x,bv.x,acc[0][0]); acc[0][1]=fmaf(av.x,bv.y,acc[0][1]);
                acc[0][2]=fmaf(av.x,bv.z,acc[0][2]); acc[0][3]=fmaf(av.x,bv.w,acc[0][3]);
                acc[1][0]=fmaf(av.y,bv.x,acc[1][0]); acc[1][1]=fmaf(av.y,bv.y,acc[1][1]);
                acc[1][2]=fmaf(av.y,bv.z,acc[1][2]); acc[1][3]=fmaf(av.y,bv.w,acc[1][3]);
                acc[2][0]=fmaf(av.z,bv.x,acc[2][0]); acc[2][1]=fmaf(av.z,bv.y,acc[2][1]);
                acc[2][2]=fmaf(av.z,bv.z,acc[2][2]); acc[2][3]=fmaf(av.z,bv.w,acc[2][3]);
                acc[3][0]=fmaf(av.w,bv.x,acc[3][0]); acc[3][1]=fmaf(av.w,bv.y,acc[3][1]);
                acc[3][2]=fmaf(av.w,bv.z,acc[3][2]); acc[3][3]=fmaf(av.w,bv.w,acc[3][3]);
            }
        }
#pragma unroll
        for (int i = 0; i < 4; ++i) {
            float4 o; o.x=acc[i][0]; o.y=acc[i][1]; o.z=acc[i][2]; o.w=acc[i][3];
            *(float4*)(Gb + (size_t)(I+rm+i) * NT + J + rn) = o;
        }
    } else if (r < 14) {
        int c = r - 6;
        float* Ks   = pool;
        float* Gd   = pool + 4224;
        float* A0   = pool + 5280;
        float* A1   = pool + 6432;
        float* Xs   = pool + 7584;
        float* evec = pool + 8736;
        float* rvec = pool + 8768;
        float* tvec = pool + 8800;

        {
            int kr = tid >> 3, seg = (tid & 7) * 16;
            const float* src = Kb + (size_t)(32*c + kr) * ND + seg;
#pragma unroll
            for (int p = 0; p < 4; ++p)
                *(float4*)(Ks + kr*132 + seg + 4*p) = *(const float4*)(src + 4*p);
        }
#pragma unroll
        for (int rep = 0; rep < 4; ++rep) {
            int id2 = rep * 256 + tid;
            int i2 = id2 >> 5, j2 = id2 & 31;
            A0[i2*36 + j2] = 0.f;
            Xs[i2*36 + j2] = (i2 == j2) ? 1.f : 0.f;
        }
        if (tid < 32) {
            evec[tid] = g_eta[b * NT + 32*c + tid];
            rvec[tid] = 1.0f - g_alpha[b * NT + 32*c + tid];
            tvec[tid] = g_theta[b * NT + 32*c + tid];
        }
        __syncthreads();

        {
            int i2 = tid >> 3, j2b = (tid & 7) * 4;
            float gq0=0.f, gq1=0.f, gq2=0.f, gq3=0.f;
#pragma unroll 8
            for (int d = 0; d < ND; ++d) {
                float a = Ks[i2*132 + d];
                gq0 = fmaf(a, Ks[(j2b+0)*132 + d], gq0);
                gq1 = fmaf(a, Ks[(j2b+1)*132 + d], gq1);
                gq2 = fmaf(a, Ks[(j2b+2)*132 + d], gq2);
                gq3 = fmaf(a, Ks[(j2b+3)*132 + d], gq3);
            }
            Gd[i2*33 + j2b+0] = gq0;
            Gd[i2*33 + j2b+1] = gq1;
            Gd[i2*33 + j2b+2] = gq2;
            Gd[i2*33 + j2b+3] = gq3;
        }
        __syncthreads();

        if (tid < 32) {
            int tau2 = tid;
            float th = tvec[tau2];
            float h = 1.f, pp = 1.f;
            for (int j2 = tau2 + 1; j2 < 32; ++j2) {
                float d = -th * Gd[j2*33 + tau2] * h;
                A0[j2*36 + tau2] = d;
                Xs[j2*36 + tau2] = d;
                pp *= evec[j2];
                h = fmaf(rvec[j2], h, pp);
            }
        }
        __syncthreads();

        int rr = tid >> 3;
        int c0 = (tid & 7) * 4;
        float* Acur = A0;
        float* Anxt = A1;
#pragma unroll
        for (int it = 0; it < 4; ++it) {
            float4 acc = make_float4(0.f, 0.f, 0.f, 0.f);
#pragma unroll 8
            for (int kk = 0; kk < 32; ++kk) {
                float a = Acur[rr*36 + kk];
                float4 bv = *(const float4*)&Acur[kk*36 + c0];
                acc.x = fmaf(a, bv.x, acc.x);
                acc.y = fmaf(a, bv.y, acc.y);
                acc.z = fmaf(a, bv.z, acc.z);
                acc.w = fmaf(a, bv.w, acc.w);
            }
            *(float4*)&Anxt[rr*36 + c0] = acc;
            __syncthreads();

            float4 xa = make_float4(0.f, 0.f, 0.f, 0.f);
#pragma unroll 8
            for (int kk = 0; kk < 32; ++kk) {
                float a = Xs[rr*36 + kk];
                float4 bv = *(const float4*)&Anxt[kk*36 + c0];
                xa.x = fmaf(a, bv.x, xa.x);
                xa.y = fmaf(a, bv.y, xa.y);
                xa.z = fmaf(a, bv.z, xa.z);
                xa.w = fmaf(a, bv.w, xa.w);
            }
            __syncthreads();
            float4 xo = *(const float4*)&Xs[rr*36 + c0];
            xo.x += xa.x; xo.y += xa.y; xo.z += xa.z; xo.w += xa.w;
            *(float4*)&Xs[rr*36 + c0] = xo;
            __syncthreads();

            float* tmp = Acur; Acur = Anxt; Anxt = tmp;
        }

        float* Xo = g_X + (size_t)(b * 8 + c) * 1024;
#pragma unroll
        for (int rep = 0; rep < 4; ++rep) {
            int id2 = rep * 256 + tid;
            Xo[id2] = Xs[(id2 >> 5) * 36 + (id2 & 31)];
        }
    } else {
        // ---- 4 cross blocks + Gq (one CTA) ----
        cross_block(Kb, Gb, pool, 1, 0, tid);
        cross_block(Kb, Gb, pool, 3, 2, tid);
        cross_block(Kb, Gb, pool, 5, 4, tid);
        cross_block(Kb, Gb, pool, 7, 6, tid);
        float* qsm = pool;
        if (tid < ND) qsm[tid] = g_qlast[b * ND + tid];
        __syncthreads();
        const float* krow = Kb + (size_t)tid * ND;
        float acc = 0.f;
#pragma unroll 8
        for (int d = 0; d < ND; ++d) acc = fmaf(krow[d], qsm[d], acc);
        g_Gq[b * NT + tid] = acc;
    }

    __threadfence();
    __syncthreads();
    if (tid == 0) sflag = atomicAdd(&g_ctr[b], 1);
    __syncthreads();
    if (sflag != 14) return;
    __threadfence();

    // ================= tail: coefs + z-solve + m_last + head =========
    float (*sHc)[NT]  = (float(*)[NT])(pool);
    float (*sPPc)[NT] = (float(*)[NT])(pool + 2048);
    float* sA    = pool + 4096;
    float* sB    = pool + 4352;
    float* mc    = pool + 4608;
    float* zvec  = pool + 4864;
    float* eta_s = pool + 5120;
    float* r_s   = pool + 5376;
    float* Xc    = pool + 5632;
    float* pbuff = pool + 6688;
    float* rbuf  = pool + 6952;
    float* red   = pool + 6984;
    float* A32s  = pool + 7240;
    float* B32s  = pool + 7248;
    float* E32s  = pool + 7256;
    float* zh    = pool + 7264;
    float* fusedv= pool + 7520;
    float* tbuf  = pool + 7648;
    float* hhs   = pool + 7776;

    int tau = tid;
    __syncthreads();
    eta_s[tid] = g_eta[b * NT + tid];
    r_s[tid]   = 1.0f - g_alpha[b * NT + tid];
    float th   = g_theta[b * NT + tau];
    float gqv  = g_Gq[b * NT + tau];
    __syncthreads();

    if (tid < 8) {
        int c0 = tid * 32;
        float A = 1.f, Bv = 0.f, E = 1.f;
        for (int j = 0; j < 32; ++j) {
            sA[c0 + j] = A;
            sB[c0 + j] = Bv;
            E *= eta_s[c0 + j];
            Bv = fmaf(r_s[c0 + j], Bv, E);
            A *= r_s[c0 + j];
        }
        A32s[tid] = A; B32s[tid] = Bv; E32s[tid] = E;
    }
    __syncthreads();

    {
        int Ct = tau >> 5;
        float h = 1.f, pp = 1.f;
        int c1 = 32 * (Ct + 1);
        for (int t = tau + 1; t < c1; ++t) {
            pp *= eta_s[t];
            h = fmaf(r_s[t], h, pp);
        }
        for (int C = Ct + 1; C < 8; ++C) {
            sHc[C][tau]  = -th * h;
            sPPc[C][tau] = -th * pp;
            h = fmaf(A32s[C], h, B32s[C] * pp);
            pp *= E32s[C];
        }
        mc[tau] = -th * h * gqv;
    }
    __syncthreads();

    int u = tid & 31, w = tid >> 5;
    const float* Xob = g_X + (size_t)b * 8 * 1024;

    zchunk_f<7>(Gb, Xob, Xc, pbuff, rbuf, zvec, mc, sA, sB, sHc, sPPc, tid, u, w);
    zchunk_f<6>(Gb, Xob, Xc, pbuff, rbuf, zvec, mc, sA, sB, sHc, sPPc, tid, u, w);
    zchunk_f<5>(Gb, Xob, Xc, pbuff, rbuf, zvec, mc, sA, sB, sHc, sPPc, tid, u, w);
    zchunk_f<4>(Gb, Xob, Xc, pbuff, rbuf, zvec, mc, sA, sB, sHc, sPPc, tid, u, w);
    zchunk_f<3>(Gb, Xob, Xc, pbuff, rbuf, zvec, mc, sA, sB, sHc, sPPc, tid, u, w);
    zchunk_f<2>(Gb, Xob, Xc, pbuff, rbuf, zvec, mc, sA, sB, sHc, sPPc, tid, u, w);
    zchunk_f<1>(Gb, Xob, Xc, pbuff, rbuf, zvec, mc, sA, sB, sHc, sPPc, tid, u, w);
    zchunk_f<0>(Gb, Xob, Xc, pbuff, rbuf, zvec, mc, sA, sB, sHc, sPPc, tid, u, w);

    // ---- m_last = -V^T z (2-way K split) ----
    {
        int i = tid & 127, hf = tid >> 7;
        const float* vb = g_v + (size_t)b * NT * ND;
        float a = 0.f;
        int tb = hf * 128;
#pragma unroll 16
        for (int t = 0; t < 128; ++t)
            a = fmaf(vb[(size_t)(tb + t) * ND + i], zvec[tb + t], a);
        red[hf * 128 + i] = a;
    }
    __syncthreads();

    // ---- head chain ----
    if (tid < ND) {
        zh[ND + tid] = -(red[tid] + red[128 + tid]);
        zh[tid] = g_flast[b * ND + tid];
    }
    __syncthreads();

    {
        int o = tid & 127, hf = tid >> 7;
        float acc = 0.f;
        int ib = hf * 128;
#pragma unroll 16
        for (int i = 0; i < 128; ++i)
            acc = fmaf(zh[ib + i], W_f[(size_t)(ib + i) * ND + o], acc);
        red[hf * 128 + o] = acc;
    }
    __syncthreads();
    if (tid < ND) {
        float g = sigmoid_f(red[tid] + red[128 + tid] + b_f[tid]);
        fusedv[tid] = zh[tid] * g + zh[ND + tid] * (1.0f - g);
    }
    __syncthreads();

    {
        int o = tid & 127, hf = tid >> 7;
        float acc = 0.f;
        int ib = hf * 64;
#pragma unroll 16
        for (int i = 0; i < 64; ++i)
            acc = fmaf(fusedv[ib + i], W1[(size_t)(ib + i) * ND + o], acc);
        red[hf * 128 + o] = acc;
    }
    __syncthreads();
    if (tid < ND) tbuf[tid] = red[tid] + red[128 + tid] + b1[tid];
    __syncthreads();

    float sum = 0.f, sq = 0.f;
#pragma unroll 8
    for (int i = 0; i < ND; ++i) { float t = tbuf[i]; sum += t; sq += t*t; }
    float mu = sum * (1.0f / ND);
    float var = sq * (1.0f / ND) - mu * mu;
    float rstd = rsqrtf(var + 1e-5f);
    if (tid < ND) {
        float ln = (tbuf[tid] - mu) * rstd * g1[tid] + be1[tid];
        hhs[tid] = gelu_t(ln);
        g_hh[b * ND + tid] = hhs[tid];
    }

    // signal head gate
    __threadfence();
    __syncthreads();
    if (tid == 0) atomicAdd(&g_ctr[8], 1);
}

// ---------------- launch ----------------------------------------------------
extern "C" void kernel_launch(void* const* d_in, const int* in_sizes, int n_in,
                              void* d_out, int out_size)
{
    const float* x   = (const float*)d_in[0];
    const float* W_b = (const float*)d_in[1];
    const float* b_b = (const float*)d_in[2];
    const float* Wk  = (const float*)d_in[3];
    const float* Wv  = (const float*)d_in[4];
    const float* Wq  = (const float*)d_in[5];
    const float* W_m = (const float*)d_in[6];
    const float* b_m = (const float*)d_in[7];
    const float* W_f = (const float*)d_in[8];
    const float* b_f = (const float*)d_in[9];
    const float* W1  = (const float*)d_in[10];
    const float* b1  = (const float*)d_in[11];
    const float* g1  = (const float*)d_in[12];
    const float* be1 = (const float*)d_in[13];
    const float* W2  = (const float*)d_in[14];
    const float* b2  = (const float*)d_in[15];
    float* out = (float*)d_out;

    mega3_kernel<<<128, 256>>>(x, W_b, b_b, Wk, Wv, Wq, W_m, b_m);
    gprep5_kernel<<<141, 256>>>(W_f, b_f, W1, b1, g1, be1, W2, b2, out);
}

// round 17
// speedup vs baseline: 1.6419x; 1.6419x over previous
#include <cuda_runtime.h>
#include <math.h>

#define NB 8
#define NT 256
#define NDI 64
#define ND 128
#define NROWS (NB*NT)
#define NOUT 672

__device__ float g_fm[NROWS*ND];
__device__ float g_k[NROWS*ND];
__device__ float g_v[NROWS*ND];
__device__ float g_theta[NROWS];
__device__ float g_eta[NROWS];
__device__ float g_alpha[NROWS];
__device__ float g_qlast[NB*ND];
__device__ float g_flast[NB*ND];
__device__ float g_hh[NB*ND];
__device__ float g_G[NB*NT*NT];
__device__ float g_X[NB*8*32*32];
__device__ float g_Gq[NB*NT];
__device__ int   g_ctr[16];
__device__ int   g_ctrf[32];

__device__ __forceinline__ float gelu_t(float x) {
    float x3 = x*x*x;
    return 0.5f*x*(1.0f + tanhf(0.79788456080286535588f*(x + 0.044715f*x3)));
}
__device__ __forceinline__ float sigmoid_f(float x) {
    return 1.0f/(1.0f + expf(-x));
}

// =====================================================================
// Launch 1: mega3 — 128 CTAs = 32 row-blocks x 4 subs (co-resident).
// =====================================================================
__global__ __launch_bounds__(256, 1) void mega3_kernel(
    const float* __restrict__ x,  const float* __restrict__ W_b,
    const float* __restrict__ b_b,
    const float* __restrict__ Wk, const float* __restrict__ Wv,
    const float* __restrict__ Wq,
    const float* __restrict__ Wm, const float* __restrict__ bm_)
{
    __shared__ __align__(16) float pool[9216];

    int tid = threadIdx.x;
    int idx = blockIdx.x;
    if (idx == 0 && tid < 16) g_ctr[tid] = 0;

    int rb = idx >> 2, sub = idx & 3;
    int row0 = rb * 64;
    int srow0 = row0 + sub * 16;

    // ---------------- Phase A: f slice (16 x 128) ----------------
    {
        float* Wbs = pool;
        float* xs  = pool + 8192;
        const float4* Wb4 = (const float4*)W_b;
#pragma unroll
        for (int rep = 0; rep < 8; ++rep)
            ((float4*)Wbs)[rep * 256 + tid] = Wb4[rep * 256 + tid];
        {
            int r = tid >> 4, q = (tid & 15) * 4;
            *(float4*)(xs + r * 64 + q) =
                *(const float4*)(x + (size_t)(srow0 + r) * NDI + q);
        }
        __syncthreads();

        int r = tid >> 4;
        int cg = (tid & 15) * 8;
        float acc[8];
#pragma unroll
        for (int j = 0; j < 8; ++j) acc[j] = 0.f;
#pragma unroll 8
        for (int k = 0; k < NDI; ++k) {
            float a = xs[r * 64 + k];
            float4 w0 = *(const float4*)(Wbs + k * 128 + cg);
            float4 w1 = *(const float4*)(Wbs + k * 128 + cg + 4);
            acc[0] = fmaf(a, w0.x, acc[0]);
            acc[1] = fmaf(a, w0.y, acc[1]);
            acc[2] = fmaf(a, w0.z, acc[2]);
            acc[3] = fmaf(a, w0.w, acc[3]);
            acc[4] = fmaf(a, w1.x, acc[4]);
            acc[5] = fmaf(a, w1.y, acc[5]);
            acc[6] = fmaf(a, w1.z, acc[6]);
            acc[7] = fmaf(a, w1.w, acc[7]);
        }
        float4 bb0 = *(const float4*)(b_b + cg);
        float4 bb1 = *(const float4*)(b_b + cg + 4);
        float4 o0, o1;
        o0.x = gelu_t(acc[0] + bb0.x);
        o0.y = gelu_t(acc[1] + bb0.y);
        o0.z = gelu_t(acc[2] + bb0.z);
        o0.w = gelu_t(acc[3] + bb0.w);
        o1.x = gelu_t(acc[4] + bb1.x);
        o1.y = gelu_t(acc[5] + bb1.y);
        o1.z = gelu_t(acc[6] + bb1.z);
        o1.w = gelu_t(acc[7] + bb1.w);
        *(float4*)(g_fm + (size_t)(srow0 + r) * ND + cg)     = o0;
        *(float4*)(g_fm + (size_t)(srow0 + r) * ND + cg + 4) = o1;
    }

    __threadfence();
    __syncthreads();
    if (tid == 0) {
        atomicAdd(&g_ctrf[rb], 1);
        while (atomicAdd(&g_ctrf[rb], 0) < 4) __nanosleep(64);
    }
    __syncthreads();
    __threadfence();

    // ---------------- Phase B: kv quarter (64x64, K=128, Kc=32) -------
    {
        const float* Bmw = (sub >> 1) ? Wv : Wk;
        float* Cout = (sub >> 1) ? g_v : g_k;
        int bn = (sub & 1) * 64;
        float* As_ = pool;            // [32][64] transposed (kcol-major)
        float* Bs_ = pool + 2048;     // [32][64] row-major
        int ar = tid >> 2, ac = (tid & 3) * 4;     // 64 rows x 16 kcols
        int br = tid >> 4, bc4 = (tid & 15) * 4;   // 16 krows x 64 cols
        int rm = (tid >> 4) * 4, rn = (tid & 15) * 4;

        float acc[4][4];
#pragma unroll
        for (int i = 0; i < 4; ++i)
#pragma unroll
            for (int j = 0; j < 4; ++j) acc[i][j] = 0.f;

        float4 pa0 = *(const float4*)(g_fm + (size_t)(row0 + ar) * ND + ac);
        float4 pa1 = *(const float4*)(g_fm + (size_t)(row0 + ar) * ND + 16 + ac);
        float4 pb0 = *(const float4*)(Bmw + (size_t)br * ND + bn + bc4);
        float4 pb1 = *(const float4*)(Bmw + (size_t)(br + 16) * ND + bn + bc4);
        for (int k0 = 0; k0 < ND; k0 += 32) {
            __syncthreads();
            As_[(ac+0)*64 + ar] = pa0.x;
            As_[(ac+1)*64 + ar] = pa0.y;
            As_[(ac+2)*64 + ar] = pa0.z;
            As_[(ac+3)*64 + ar] = pa0.w;
            As_[(16+ac+0)*64 + ar] = pa1.x;
            As_[(16+ac+1)*64 + ar] = pa1.y;
            As_[(16+ac+2)*64 + ar] = pa1.z;
            As_[(16+ac+3)*64 + ar] = pa1.w;
            *(float4*)(Bs_ + br*64 + bc4) = pb0;
            *(float4*)(Bs_ + (br+16)*64 + bc4) = pb1;
            __syncthreads();
            if (k0 + 32 < ND) {
                pa0 = *(const float4*)(g_fm + (size_t)(row0 + ar) * ND + k0 + 32 + ac);
                pa1 = *(const float4*)(g_fm + (size_t)(row0 + ar) * ND + k0 + 48 + ac);
                pb0 = *(const float4*)(Bmw + (size_t)(k0 + 32 + br) * ND + bn + bc4);
                pb1 = *(const float4*)(Bmw + (size_t)(k0 + 48 + br) * ND + bn + bc4);
            }
#pragma unroll
            for (int kk = 0; kk < 32; ++kk) {
                float4 av = *(const float4*)(As_ + kk*64 + rm);
                float4 bv = *(const float4*)(Bs_ + kk*64 + rn);
                acc[0][0]=fmaf(av.x,bv.x,acc[0][0]); acc[0][1]=fmaf(av.x,bv.y,acc[0][1]);
                acc[0][2]=fmaf(av.x,bv.z,acc[0][2]); acc[0][3]=fmaf(av.x,bv.w,acc[0][3]);
                acc[1][0]=fmaf(av.y,bv.x,acc[1][0]); acc[1][1]=fmaf(av.y,bv.y,acc[1][1]);
                acc[1][2]=fmaf(av.y,bv.z,acc[1][2]); acc[1][3]=fmaf(av.y,bv.w,acc[1][3]);
                acc[2][0]=fmaf(av.z,bv.x,acc[2][0]); acc[2][1]=fmaf(av.z,bv.y,acc[2][1]);
                acc[2][2]=fmaf(av.z,bv.z,acc[2][2]); acc[2][3]=fmaf(av.z,bv.w,acc[2][3]);
                acc[3][0]=fmaf(av.w,bv.x,acc[3][0]); acc[3][1]=fmaf(av.w,bv.y,acc[3][1]);
                acc[3][2]=fmaf(av.w,bv.z,acc[3][2]); acc[3][3]=fmaf(av.w,bv.w,acc[3][3]);
            }
        }
#pragma unroll
        for (int i = 0; i < 4; ++i) {
            float4 o;
            o.x = acc[i][0]; o.y = acc[i][1]; o.z = acc[i][2]; o.w = acc[i][3];
            *(float4*)(Cout + (size_t)(row0 + rm + i) * ND + bn + rn) = o;
        }
    }

    // ---------------- meta (sub 0) ----------------
    if (sub == 0) {
        int warp = tid >> 5, lane = tid & 31;
        const float* wp = Wm + lane * 12;
        float w0=wp[0],w1=wp[1],w2=wp[2],w3=wp[3],w4=wp[4],w5=wp[5];
        float w6=wp[6],w7=wp[7],w8=wp[8],w9=wp[9],w10=wp[10],w11=wp[11];
#pragma unroll
        for (int rr = 0; rr < 8; ++rr) {
            int row = row0 + warp * 8 + rr;
            float4 fv = ((const float4*)(g_fm + (size_t)row * ND))[lane];
            float d0 = fv.x*w0 + fv.y*w3 + fv.z*w6 + fv.w*w9;
            float d1 = fv.x*w1 + fv.y*w4 + fv.z*w7 + fv.w*w10;
            float d2 = fv.x*w2 + fv.y*w5 + fv.z*w8 + fv.w*w11;
#pragma unroll
            for (int o = 16; o > 0; o >>= 1) {
                d0 += __shfl_xor_sync(0xffffffffu, d0, o);
                d1 += __shfl_xor_sync(0xffffffffu, d1, o);
                d2 += __shfl_xor_sync(0xffffffffu, d2, o);
            }
            if (lane == 0) {
                g_theta[row] = 0.01f * sigmoid_f(d0 + bm_[0]);
                g_eta[row]   =         sigmoid_f(d1 + bm_[1]);
                g_alpha[row] = 0.1f  * sigmoid_f(d2 + bm_[2]);
            }
        }
    }

    // ---------------- qlast + f_last (sub 1, last row-block) ---------
    if (sub == 1 && (rb & 3) == 3) {
        int batch = rb >> 2;
        __syncthreads();
        float* fl = pool;
        float* part = pool + 128;
        if (tid < ND)
            fl[tid] = g_fm[(size_t)(row0 + 63) * ND + tid];
        __syncthreads();
        int j = tid & 127, hf = tid >> 7;
        float a = 0.f;
        int i0 = hf * 64;
#pragma unroll 8
        for (int i = 0; i < 64; ++i)
            a = fmaf(fl[i0 + i], Wq[(size_t)(i0 + i) * ND + j], a);
        part[hf * 128 + j] = a;
        __syncthreads();
        if (tid < ND) {
            g_qlast[batch * ND + tid] = part[tid] + part[128 + tid];
            g_flast[batch * ND + tid] = fl[tid];
        }
    }
}

// =====================================================================
// zchunk: one fully-unrolled back-substitution chunk.
// =====================================================================
template<int C>
__device__ __forceinline__ void zchunk_f(
    const float* __restrict__ Gb, const float* __restrict__ Xob,
    float* Xc, float* pbuff, float* rbuf, float* zvec, const float* mc,
    const float* sA, const float* sB,
    const float (*sHc)[NT], const float (*sPPc)[NT],
    int tid, int u, int w)
{
    const float* Xo = Xob + (size_t)C * 1024;
#pragma unroll
    for (int rep = 0; rep < 4; ++rep) {
        int id2 = rep * 256 + tid;
        Xc[(id2 >> 5) * 33 + (id2 & 31)] = Xo[id2];
    }
    float acc = 0.f;
    constexpr int nj = 4 * (7 - C);
    int tauc = 32 * C + u;
#pragma unroll
    for (int j = 0; j < nj; ++j) {
        int t = 32 * (C + 1) + j * 8 + w;
        int Cr = t >> 5;
        float ht = fmaf(sA[t], sHc[Cr][tauc], sB[t] * sPPc[Cr][tauc]);
        float wv = Gb[(size_t)t * NT + tauc] * ht;
        acc = fmaf(wv, zvec[t], acc);
    }
    pbuff[w * 33 + u] = acc;
    __syncthreads();
    if (tid < 32) {
        float s = mc[32*C + tid];
#pragma unroll
        for (int p = 0; p < 8; ++p) s += pbuff[p * 33 + tid];
        rbuf[tid] = s;
    }
    __syncthreads();
    {
        float a = 0.f;
#pragma unroll
        for (int q2 = 0; q2 < 4; ++q2) {
            int kk = w * 4 + q2;
            a = fmaf(Xc[kk * 33 + u], rbuf[kk], a);
        }
        pbuff[w * 33 + u] = a;
    }
    __syncthreads();
    if (tid < 32) {
        float s = 0.f;
#pragma unroll
        for (int p = 0; p < 8; ++p) s += pbuff[p * 33 + tid];
        zvec[32*C + tid] = s;
    }
    __syncthreads();
}

// =====================================================================
// Launch 2: gprep4 — 152 CTAs = 8 batches x 19. Last arriver per batch
// runs coefs + z-solve + m_last + FULL head chain -> g_hh.
// =====================================================================
__global__ __launch_bounds__(256, 1) void gprep4_kernel(
    const float* __restrict__ W_f, const float* __restrict__ b_f,
    const float* __restrict__ W1,  const float* __restrict__ b1,
    const float* __restrict__ g1,  const float* __restrict__ be1)
{
    __shared__ __align__(16) float pool[8832];
    __shared__ int sflag;

    int idx = blockIdx.x;
    int b = idx / 19;
    int r = idx % 19;
    int tid = threadIdx.x;
    const float* Kb = g_k + (size_t)b * NT * ND;
    float* Gb = g_G + (size_t)b * NT * NT;

    if (r < 6) {
        const int tiv[6] = {1, 2, 2, 3, 3, 3};
        const int tjv[6] = {0, 0, 1, 0, 1, 2};
        int I = tiv[r] * 64, J = tjv[r] * 64;
        float* As_ = pool;            // [32][64] transposed
        float* Bs_ = pool + 2048;     // [32][64] transposed
        int ar = tid >> 2, ac = (tid & 3) * 4;
        int rm = (tid >> 4) * 4, rn = (tid & 15) * 4;

        float acc[4][4];
#pragma unroll
        for (int i = 0; i < 4; ++i)
#pragma unroll
            for (int j = 0; j < 4; ++j) acc[i][j] = 0.f;

        float4 pa0 = *(const float4*)(Kb + (size_t)(I + ar) * ND + ac);
        float4 pa1 = *(const float4*)(Kb + (size_t)(I + ar) * ND + 16 + ac);
        float4 pb0 = *(const float4*)(Kb + (size_t)(J + ar) * ND + ac);
        float4 pb1 = *(const float4*)(Kb + (size_t)(J + ar) * ND + 16 + ac);
        for (int k0 = 0; k0 < ND; k0 += 32) {
            __syncthreads();
            As_[(ac+0)*64 + ar] = pa0.x;
            As_[(ac+1)*64 + ar] = pa0.y;
            As_[(ac+2)*64 + ar] = pa0.z;
            As_[(ac+3)*64 + ar] = pa0.w;
            As_[(16+ac+0)*64 + ar] = pa1.x;
            As_[(16+ac+1)*64 + ar] = pa1.y;
            As_[(16+ac+2)*64 + ar] = pa1.z;
            As_[(16+ac+3)*64 + ar] = pa1.w;
            Bs_[(ac+0)*64 + ar] = pb0.x;
            Bs_[(ac+1)*64 + ar] = pb0.y;
            Bs_[(ac+2)*64 + ar] = pb0.z;
            Bs_[(ac+3)*64 + ar] = pb0.w;
            Bs_[(16+ac+0)*64 + ar] = pb1.x;
            Bs_[(16+ac+1)*64 + ar] = pb1.y;
            Bs_[(16+ac+2)*64 + ar] = pb1.z;
            Bs_[(16+ac+3)*64 + ar] = pb1.w;
            __syncthreads();
            if (k0 + 32 < ND) {
                pa0 = *(const float4*)(Kb + (size_t)(I + ar) * ND + k0 + 32 + ac);
                pa1 = *(const float4*)(Kb + (size_t)(I + ar) * ND + k0 + 48 + ac);
                pb0 = *(const float4*)(Kb + (size_t)(J + ar) * ND + k0 + 32 + ac);
                pb1 = *(const float4*)(Kb + (size_t)(J + ar) * ND + k0 + 48 + ac);
            }
#pragma unroll
            for (int kk = 0; kk < 32; ++kk) {
                float4 av = *(const float4*)(As_ + kk*64 + rm);
                float4 bv = *(const float4*)(Bs_ + kk*64 + rn);
                acc[0][0]=fmaf(av.x,bv.x,acc[0][0]); acc[0][1]=fmaf(av.x,bv.y,acc[0][1]);
                acc[0][2]=fmaf(av.x,bv.z,acc[0][2]); acc[0][3]=fmaf(av.x,bv.w,acc[0][3]);
                acc[1][0]=fmaf(av.y,bv.x,acc[1][0]); acc[1][1]=fmaf(av.y,bv.y,acc[1][1]);
                acc[1][2]=fmaf(av.y,bv.z,acc[1][2]); acc[1][3]=fmaf(av.y,bv.w,acc[1][3]);
                acc[2][0]=fmaf(av.z,bv.x,acc[2][0]); acc[2][1]=fmaf(av.z,bv.y,acc[2][1]);
                acc[2][2]=fmaf(av.z,bv.z,acc[2][2]); acc[2][3]=fmaf(av.z,bv.w,acc[2][3]);
                acc[3][0]=fmaf(av.w,bv.x,acc[3][0]); acc[3][1]=fmaf(av.w,bv.y,acc[3][1]);
                acc[3][2]=fmaf(av.w,bv.z,acc[3][2]); acc[3][3]=fmaf(av.w,bv.w,acc[3][3]);
            }
        }
#pragma unroll
        for (int i = 0; i < 4; ++i) {
            float4 o; o.x=acc[i][0]; o.y=acc[i][1]; o.z=acc[i][2]; o.w=acc[i][3];
            *(float4*)(Gb + (size_t)(I+rm+i) * NT + J + rn) = o;
        }
    } else if (r < 14) {
        int c = r - 6;
        float* Ks   = pool;
        float* Gd   = pool + 4224;
        float* A0   = pool + 5280;
        float* A1   = pool + 6432;
        float* Xs   = pool + 7584;
        float* evec = pool + 8736;
        float* rvec = pool + 8768;
        float* tvec = pool + 8800;

        {
            int kr = tid >> 3, seg = (tid & 7) * 16;
            const float* src = Kb + (size_t)(32*c + kr) * ND + seg;
#pragma unroll
            for (int p = 0; p < 4; ++p)
                *(float4*)(Ks + kr*132 + seg + 4*p) = *(const float4*)(src + 4*p);
        }
#pragma unroll
        for (int rep = 0; rep < 4; ++rep) {
            int id2 = rep * 256 + tid;
            int i2 = id2 >> 5, j2 = id2 & 31;
            A0[i2*36 + j2] = 0.f;
            Xs[i2*36 + j2] = (i2 == j2) ? 1.f : 0.f;
        }
        if (tid < 32) {
            evec[tid] = g_eta[b * NT + 32*c + tid];
            rvec[tid] = 1.0f - g_alpha[b * NT + 32*c + tid];
            tvec[tid] = g_theta[b * NT + 32*c + tid];
        }
        __syncthreads();

        {
            int i2 = tid >> 3, j2b = (tid & 7) * 4;
            float gq0=0.f, gq1=0.f, gq2=0.f, gq3=0.f;
#pragma unroll 8
            for (int d = 0; d < ND; ++d) {
                float a = Ks[i2*132 + d];
                gq0 = fmaf(a, Ks[(j2b+0)*132 + d], gq0);
                gq1 = fmaf(a, Ks[(j2b+1)*132 + d], gq1);
                gq2 = fmaf(a, Ks[(j2b+2)*132 + d], gq2);
                gq3 = fmaf(a, Ks[(j2b+3)*132 + d], gq3);
            }
            Gd[i2*33 + j2b+0] = gq0;
            Gd[i2*33 + j2b+1] = gq1;
            Gd[i2*33 + j2b+2] = gq2;
            Gd[i2*33 + j2b+3] = gq3;
        }
        __syncthreads();

        if (tid < 32) {
            int tau2 = tid;
            float th = tvec[tau2];
            float h = 1.f, pp = 1.f;
            for (int j2 = tau2 + 1; j2 < 32; ++j2) {
                float d = -th * Gd[j2*33 + tau2] * h;
                A0[j2*36 + tau2] = d;
                Xs[j2*36 + tau2] = d;
                pp *= evec[j2];
                h = fmaf(rvec[j2], h, pp);
            }
        }
        __syncthreads();

        int rr = tid >> 3;
        int c0 = (tid & 7) * 4;
        float* Acur = A0;
        float* Anxt = A1;
#pragma unroll
        for (int it = 0; it < 4; ++it) {
            float4 acc = make_float4(0.f, 0.f, 0.f, 0.f);
#pragma unroll 8
            for (int kk = 0; kk < 32; ++kk) {
                float a = Acur[rr*36 + kk];
                float4 bv = *(const float4*)&Acur[kk*36 + c0];
                acc.x = fmaf(a, bv.x, acc.x);
                acc.y = fmaf(a, bv.y, acc.y);
                acc.z = fmaf(a, bv.z, acc.z);
                acc.w = fmaf(a, bv.w, acc.w);
            }
            *(float4*)&Anxt[rr*36 + c0] = acc;
            __syncthreads();

            float4 xa = make_float4(0.f, 0.f, 0.f, 0.f);
#pragma unroll 8
            for (int kk = 0; kk < 32; ++kk) {
                float a = Xs[rr*36 + kk];
                float4 bv = *(const float4*)&Anxt[kk*36 + c0];
                xa.x = fmaf(a, bv.x, xa.x);
                xa.y = fmaf(a, bv.y, xa.y);
                xa.z = fmaf(a, bv.z, xa.z);
                xa.w = fmaf(a, bv.w, xa.w);
            }
            __syncthreads();
            float4 xo = *(const float4*)&Xs[rr*36 + c0];
            xo.x += xa.x; xo.y += xa.y; xo.z += xa.z; xo.w += xa.w;
            *(float4*)&Xs[rr*36 + c0] = xo;
            __syncthreads();

            float* tmp = Acur; Acur = Anxt; Anxt = tmp;
        }

        float* Xo = g_X + (size_t)(b * 8 + c) * 1024;
#pragma unroll
        for (int rep = 0; rep < 4; ++rep) {
            int id2 = rep * 256 + tid;
            Xo[id2] = Xs[(id2 >> 5) * 36 + (id2 & 31)];
        }
    } else if (r < 18) {
        int q = r - 14;
        float* Ks = pool;
        float* Kt = pool + 4224;
        {
            int kr = tid >> 3, seg = (tid & 7) * 16;
            const float* srcR = Kb + (size_t)(32*(2*q+1) + kr) * ND + seg;
            const float* srcC = Kb + (size_t)(32*(2*q)   + kr) * ND + seg;
#pragma unroll
            for (int p = 0; p < 4; ++p) {
                *(float4*)(Ks + kr*132 + seg + 4*p) = *(const float4*)(srcR + 4*p);
                *(float4*)(Kt + kr*132 + seg + 4*p) = *(const float4*)(srcC + 4*p);
            }
        }
        __syncthreads();
        {
            int i2 = tid >> 3, j2b = (tid & 7) * 4;
            float gq0=0.f, gq1=0.f, gq2=0.f, gq3=0.f;
#pragma unroll 8
            for (int d = 0; d < ND; ++d) {
                float a = Ks[i2*132 + d];
                gq0 = fmaf(a, Kt[(j2b+0)*132 + d], gq0);
                gq1 = fmaf(a, Kt[(j2b+1)*132 + d], gq1);
                gq2 = fmaf(a, Kt[(j2b+2)*132 + d], gq2);
                gq3 = fmaf(a, Kt[(j2b+3)*132 + d], gq3);
            }
            float4 o; o.x=gq0; o.y=gq1; o.z=gq2; o.w=gq3;
            *(float4*)(Gb + (size_t)(32*(2*q+1) + i2) * NT + 32*(2*q) + j2b) = o;
        }
    } else {
        float* qsm = pool;
        if (tid < ND) qsm[tid] = g_qlast[b * ND + tid];
        __syncthreads();
        const float* krow = Kb + (size_t)tid * ND;
        float acc = 0.f;
#pragma unroll 8
        for (int d = 0; d < ND; ++d) acc = fmaf(krow[d], qsm[d], acc);
        g_Gq[b * NT + tid] = acc;
    }

    __threadfence();
    __syncthreads();
    if (tid == 0) sflag = atomicAdd(&g_ctr[b], 1);
    __syncthreads();
    if (sflag != 18) return;
    __threadfence();

    // ================= tail: coefs + z-solve + m_last + head =========
    float (*sHc)[NT]  = (float(*)[NT])(pool);
    float (*sPPc)[NT] = (float(*)[NT])(pool + 2048);
    float* sA    = pool + 4096;
    float* sB    = pool + 4352;
    float* mc    = pool + 4608;
    float* zvec  = pool + 4864;
    float* eta_s = pool + 5120;
    float* r_s   = pool + 5376;
    float* Xc    = pool + 5632;
    float* pbuff = pool + 6688;
    float* rbuf  = pool + 6952;
    float* red   = pool + 6984;
    float* A32s  = pool + 7240;
    float* B32s  = pool + 7248;
    float* E32s  = pool + 7256;
    float* zh    = pool + 7264;
    float* fusedv= pool + 7520;
    float* tbuf  = pool + 7648;
    float* hhs   = pool + 7776;

    int tau = tid;
    __syncthreads();
    eta_s[tid] = g_eta[b * NT + tid];
    r_s[tid]   = 1.0f - g_alpha[b * NT + tid];
    float th   = g_theta[b * NT + tau];
    float gqv  = g_Gq[b * NT + tau];
    __syncthreads();

    if (tid < 8) {
        int c0 = tid * 32;
        float A = 1.f, Bv = 0.f, E = 1.f;
        for (int j = 0; j < 32; ++j) {
            sA[c0 + j] = A;
            sB[c0 + j] = Bv;
            E *= eta_s[c0 + j];
            Bv = fmaf(r_s[c0 + j], Bv, E);
            A *= r_s[c0 + j];
        }
        A32s[tid] = A; B32s[tid] = Bv; E32s[tid] = E;
    }
    __syncthreads();

    {
        int Ct = tau >> 5;
        float h = 1.f, pp = 1.f;
        int c1 = 32 * (Ct + 1);
        for (int t = tau + 1; t < c1; ++t) {
            pp *= eta_s[t];
            h = fmaf(r_s[t], h, pp);
        }
        for (int C = Ct + 1; C < 8; ++C) {
            sHc[C][tau]  = -th * h;
            sPPc[C][tau] = -th * pp;
            h = fmaf(A32s[C], h, B32s[C] * pp);
            pp *= E32s[C];
        }
        mc[tau] = -th * h * gqv;
    }
    __syncthreads();

    int u = tid & 31, w = tid >> 5;
    const float* Xob = g_X + (size_t)b * 8 * 1024;

    zchunk_f<7>(Gb, Xob, Xc, pbuff, rbuf, zvec, mc, sA, sB, sHc, sPPc, tid, u, w);
    zchunk_f<6>(Gb, Xob, Xc, pbuff, rbuf, zvec, mc, sA, sB, sHc, sPPc, tid, u, w);
    zchunk_f<5>(Gb, Xob, Xc, pbuff, rbuf, zvec, mc, sA, sB, sHc, sPPc, tid, u, w);
    zchunk_f<4>(Gb, Xob, Xc, pbuff, rbuf, zvec, mc, sA, sB, sHc, sPPc, tid, u, w);
    zchunk_f<3>(Gb, Xob, Xc, pbuff, rbuf, zvec, mc, sA, sB, sHc, sPPc, tid, u, w);
    zchunk_f<2>(Gb, Xob, Xc, pbuff, rbuf, zvec, mc, sA, sB, sHc, sPPc, tid, u, w);
    zchunk_f<1>(Gb, Xob, Xc, pbuff, rbuf, zvec, mc, sA, sB, sHc, sPPc, tid, u, w);
    zchunk_f<0>(Gb, Xob, Xc, pbuff, rbuf, zvec, mc, sA, sB, sHc, sPPc, tid, u, w);

    // ---- m_last = -V^T z (2-way K split) ----
    {
        int i = tid & 127, hf = tid >> 7;
        const float* vb = g_v + (size_t)b * NT * ND;
        float a = 0.f;
        int tb = hf * 128;
#pragma unroll 16
        for (int t = 0; t < 128; ++t)
            a = fmaf(vb[(size_t)(tb + t) * ND + i], zvec[tb + t], a);
        red[hf * 128 + i] = a;
    }
    __syncthreads();

    // ---- head chain (f_last | m_last all in smem) ----
    if (tid < ND) {
        zh[ND + tid] = -(red[tid] + red[128 + tid]);
        zh[tid] = g_flast[b * ND + tid];
    }
    __syncthreads();

    {
        int o = tid & 127, hf = tid >> 7;
        float acc = 0.f;
        int ib = hf * 128;
#pragma unroll 16
        for (int i = 0; i < 128; ++i)
            acc = fmaf(zh[ib + i], W_f[(size_t)(ib + i) * ND + o], acc);
        red[hf * 128 + o] = acc;
    }
    __syncthreads();
    if (tid < ND) {
        float g = sigmoid_f(red[tid] + red[128 + tid] + b_f[tid]);
        fusedv[tid] = zh[tid] * g + zh[ND + tid] * (1.0f - g);
    }
    __syncthreads();

    {
        int o = tid & 127, hf = tid >> 7;
        float acc = 0.f;
        int ib = hf * 64;
#pragma unroll 16
        for (int i = 0; i < 64; ++i)
            acc = fmaf(fusedv[ib + i], W1[(size_t)(ib + i) * ND + o], acc);
        red[hf * 128 + o] = acc;
    }
    __syncthreads();
    if (tid < ND) tbuf[tid] = red[tid] + red[128 + tid] + b1[tid];
    __syncthreads();

    float sum = 0.f, sq = 0.f;
#pragma unroll 8
    for (int i = 0; i < ND; ++i) { float t = tbuf[i]; sum += t; sq += t*t; }
    float mu = sum * (1.0f / ND);
    float var = sq * (1.0f / ND) - mu * mu;
    float rstd = rsqrtf(var + 1e-5f);
    if (tid < ND) {
        float ln = (tbuf[tid] - mu) * rstd * g1[tid] + be1[tid];
        hhs[tid] = gelu_t(ln);
        g_hh[b * ND + tid] = hhs[tid];
    }
}

// =====================================================================
// Launch 3: head4 — 21 CTAs, pure out = h @ W2 + b2 (g_hh ready).
// =====================================================================
__global__ __launch_bounds__(256, 1) void head4_kernel(
    const float* __restrict__ W2, const float* __restrict__ b2,
    float* __restrict__ out)
{
    __shared__ __align__(16) float pool2[5600];
    int tid = threadIdx.x;
    int bx = blockIdx.x;

    if (bx == 0 && tid < 32) g_ctrf[tid] = 0;

    int col0 = bx * 32;
    float* w2s = pool2;            // [128][33]
    float* hs  = pool2 + 4224;     // [8][132]

#pragma unroll
    for (int rep = 0; rep < 4; ++rep) {
        int id2 = rep * 256 + tid;
        int row = id2 >> 3;
        int quad = (id2 & 7) * 4;
        float4 v = *(const float4*)(W2 + (size_t)row * NOUT + col0 + quad);
        w2s[row*33 + quad + 0] = v.x;
        w2s[row*33 + quad + 1] = v.y;
        w2s[row*33 + quad + 2] = v.z;
        w2s[row*33 + quad + 3] = v.w;
    }
#pragma unroll
    for (int rep = 0; rep < 4; ++rep) {
        int id2 = rep * 256 + tid;
        if (id2 < 1024) {
            int bb = id2 >> 7, i = id2 & 127;
            hs[bb * 132 + i] = g_hh[bb * ND + i];
        }
    }
    __syncthreads();

    int c = tid & 31, b = tid >> 5;
    float acc = b2[col0 + c];
#pragma unroll 16
    for (int i = 0; i < 128; ++i)
        acc = fmaf(hs[b * 132 + i], w2s[i * 33 + c], acc);
    out[b * NOUT + col0 + c] = acc;
}

// ---------------- launch ----------------------------------------------------
extern "C" void kernel_launch(void* const* d_in, const int* in_sizes, int n_in,
                              void* d_out, int out_size)
{
    const float* x   = (const float*)d_in[0];
    const float* W_b = (const float*)d_in[1];
    const float* b_b = (const float*)d_in[2];
    const float* Wk  = (const float*)d_in[3];
    const float* Wv  = (const float*)d_in[4];
    const float* Wq  = (const float*)d_in[5];
    const float* W_m = (const float*)d_in[6];
    const float* b_m = (const float*)d_in[7];
    const float* W_f = (const float*)d_in[8];
    const float* b_f = (const float*)d_in[9];
    const float* W1  = (const float*)d_in[10];
    const float* b1  = (const float*)d_in[11];
    const float* g1  = (const float*)d_in[12];
    const float* be1 = (const float*)d_in[13];
    const float* W2  = (const float*)d_in[14];
    const float* b2  = (const float*)d_in[15];
    float* out = (float*)d_out;

    mega3_kernel<<<128, 256>>>(x, W_b, b_b, Wk, Wv, Wq, W_m, b_m);
    gprep4_kernel<<<NB * 19, 256>>>(W_f, b_f, W1, b1, g1, be1);
    head4_kernel<<<21, 256>>>(W2, b2, out);
}